// round 16
// baseline (speedup 1.0000x reference)
#include <cuda_runtime.h>
#include <math.h>

#define NX    4096
#define NEQ   768
#define MU    0.1
#define SIG   0.1
#define ITERS 40
#define NBLK  132
#define NTHR  256
#define SMEM_DBL 8320          // 66560 bytes dynamic shared

// ---------------- device-global state ----------------
__device__ double g_A[(size_t)NEQ * NX];
__device__ double g_AT[(size_t)NX * NEQ];
__device__ float  g_Ah[(size_t)NEQ * NX];
__device__ float  g_Al[(size_t)NEQ * NX];
__device__ float  g_Bh[(size_t)NEQ * NX];   // (A * Dinv) rounded to fp32
__device__ double g_q[NX];
__device__ double g_b[NEQ];
__device__ double g_z[NX];
__device__ double g_lam[NX];
__device__ double g_nu[NEQ];
__device__ double g_t[NX];
__device__ double g_rc[NX];
__device__ double g_Dinv[NX];
__device__ double g_rtil[NX];
__device__ double g_w[NX];
__device__ double g_dnu[NEQ];
__device__ double g_rhs[NEQ];
__device__ double g_ADA[NEQ * NEQ];
__device__ double g_invd[NEQ];           // 1/L[j][j]
__device__ double g_W[12 * 64 * 64];     // M_p = inv(L_pp)^T, row-major 64x64 per panel
__device__ double g_dz[NX];
__device__ double g_dlam[NX];
__device__ double g_part4[16 * 4];       // per-block partials of {z.lam, z.dlam, dz.lam, dz.dlam}
__device__ double g_pmin[16];
__device__ int    g_is64;
__device__ unsigned g_count;
__device__ unsigned g_flag;              // potrf-completion flag (monotonic)

__global__ void k_reset() { g_count = 0u; g_flag = 0u; }

// software grid barrier: arrive with atomic, poll with plain L2 load
__device__ __forceinline__ void gsync(unsigned &tgt) {
    __syncthreads();
    if (threadIdx.x == 0) {
        __threadfence();
        atomicAdd(&g_count, 1u);
        tgt += NBLK;
        while (*(volatile unsigned*)&g_count < tgt) __nanosleep(32);
        __threadfence();
    }
    __syncthreads();
}

// block 131 waits until g_flag >= tgt (release by block 0 after potrf)
__device__ __forceinline__ void flag_wait(unsigned tgt) {
    __syncthreads();
    if (threadIdx.x == 0) {
        while (*(volatile unsigned*)&g_flag < tgt) __nanosleep(32);
        __threadfence();
    }
    __syncthreads();
}

__device__ __forceinline__ double alpha_of() {
    double a = g_pmin[0];
#pragma unroll
    for (int j = 1; j < 16; j++) a = fmin(a, g_pmin[j]);
    return fmin(1.0, 0.99 * a);
}

__device__ __forceinline__ void blk_min_to(double v, double* s_red, int tid, double* dst) {
#pragma unroll
    for (int off = 16; off; off >>= 1) v = fmin(v, __shfl_down_sync(0xffffffffu, v, off));
    if ((tid & 31) == 0) s_red[tid >> 5] = v;
    __syncthreads();
    if (tid == 0) { double r = s_red[0]; for (int w = 1; w < 8; w++) r = fmin(r, s_red[w]); *dst = r; }
    __syncthreads();
}

// 4 simultaneous deterministic block sums -> g_part4[bid]
__device__ __forceinline__ void blk_sum4_to(double v0, double v1, double v2, double v3,
                                            double* s4, int tid, int bid) {
#pragma unroll
    for (int off = 16; off; off >>= 1) {
        v0 += __shfl_down_sync(0xffffffffu, v0, off);
        v1 += __shfl_down_sync(0xffffffffu, v1, off);
        v2 += __shfl_down_sync(0xffffffffu, v2, off);
        v3 += __shfl_down_sync(0xffffffffu, v3, off);
    }
    if ((tid & 31) == 0) {
        int w = tid >> 5;
        s4[w * 4 + 0] = v0; s4[w * 4 + 1] = v1; s4[w * 4 + 2] = v2; s4[w * 4 + 3] = v3;
    }
    __syncthreads();
    if (tid == 0) {
        double a0 = 0, a1 = 0, a2 = 0, a3 = 0;
        for (int w = 0; w < 8; w++) {
            a0 += s4[w * 4]; a1 += s4[w * 4 + 1]; a2 += s4[w * 4 + 2]; a3 += s4[w * 4 + 3];
        }
        g_part4[bid * 4 + 0] = a0; g_part4[bid * 4 + 1] = a1;
        g_part4[bid * 4 + 2] = a2; g_part4[bid * 4 + 3] = a3;
    }
    __syncthreads();
}

__device__ __forceinline__ void tri_map(int t, int &bi, int &bj) {
    int b = 0;
    while ((b + 1) * (b + 2) / 2 <= t) b++;
    bi = b; bj = t - b * (b + 1) / 2;
}

// range-safe fp64 reciprocal: integer magic seed + 4 fused Newton steps
__device__ __forceinline__ double fast_rcp(double d) {
    double r = __longlong_as_double(0x7FDE6238502484BAll - __double_as_longlong(d));
#pragma unroll
    for (int s = 0; s < 4; s++) {
        double e = __fma_rn(-d, r, 1.0);
        r = __fma_rn(r, e, r);
    }
    return r;
}

// potrf of 64x64 diagonal block at offset o (one block, 256 threads).
__device__ void potrf_panel(double* sh, int o, int tid) {
    double* S   = sh;            // [64][65]
    double* wv  = sh + 4160;
    double* inv = sh + 4224;
    double* rsv = sh + 4288;
    for (int i = tid; i < 4096; i += NTHR) {
        int r = i >> 6, c = i & 63;
        S[r * 65 + c] = g_ADA[(size_t)(o + r) * NEQ + o + c];
    }
    __syncthreads();
    int r = tid & 63, q = tid >> 6;
    for (int j = 0; j < 64; j++) {
        if (q == 0) {
            double d = fmax(S[j * 65 + j], 1e-300);
            double ri = fast_rcp(d);
            if (r == j) inv[j] = ri;
            if (r > j) wv[r] = S[r * 65 + j] * ri;
        }
        __syncthreads();
        if (r > j) {
            double wr = wv[r];
            for (int c = j + 1 + q; c <= r; c += 4)
                S[r * 65 + c] -= wr * S[c * 65 + j];
        }
        __syncthreads();
    }
    if (tid < 64) {
        double rs = sqrt(inv[tid]);
        rsv[tid] = rs;
        g_invd[o + tid] = rs;
    }
    __syncthreads();
    for (int i = tid; i < 4096; i += NTHR) {
        int rr = i >> 6, c = i & 63;
        g_ADA[(size_t)(o + rr) * NEQ + o + c] = S[rr * 65 + c] * rsv[c];
    }
}

// M_p = inv(L_pp)^T via identity column sweep (one block). Writes g_W[p].
__device__ void msweep(double* sh, int p, int tid) {
    int o = p * 64;
    double* L = sh;          // [64][65]
    double* X = sh + 4160;   // [64][65]
    for (int i = tid; i < 4096; i += NTHR) {
        int r = i >> 6, c = i & 63;
        L[r * 65 + c] = g_ADA[(size_t)(o + r) * NEQ + o + c];
        X[r * 65 + c] = (r == c) ? 1.0 : 0.0;
    }
    __syncthreads();
    if (tid < 64) L[tid * 65 + tid] = g_invd[o + tid];
    __syncthreads();
    int r = tid & 63, q = tid >> 6;
    for (int j = 0; j < 64; j++) {
        if (q == 0) X[r * 65 + j] *= L[j * 65 + j];
        __syncthreads();
        double xj = X[r * 65 + j];
        for (int c = j + 1 + q; c < 64; c += 4)
            X[r * 65 + c] -= xj * L[c * 65 + j];
        __syncthreads();
    }
    for (int i = tid; i < 4096; i += NTHR) {
        int rr = i >> 6, c = i & 63;
        g_W[(size_t)p * 4096 + rr * 64 + c] = X[rr * 65 + c];
    }
}

// A @ w  (mode 0 -> g_b ; mode 1 -> g_rhs = A@w - b)
__device__ __forceinline__ void amv_phase(double* sv, int mode, int bid, int tid, int warp, int lane) {
    for (int i = tid; i < NX; i += NTHR) sv[i] = g_w[i];
    __syncthreads();
    int row = bid * 8 + warp;
    if (row < NEQ) {
        const double* ar = g_A + (size_t)row * NX;
        double s = 0.0;
        for (int k = lane; k < NX; k += 32) s += ar[k] * sv[k];
#pragma unroll
        for (int off = 16; off; off >>= 1) s += __shfl_down_sync(0xffffffffu, s, off);
        if (lane == 0) { if (mode == 0) g_b[row] = s; else g_rhs[row] = s - g_b[row]; }
    }
    __syncthreads();
}

// g_t = A^T @ x; mode 0: x = nu + alpha*dnu (on-the-fly); mode 1: x = dnu
__device__ __forceinline__ void atmv_phase(double* sx, int mode, int bid, int tid, int warp, int lane) {
    if (mode == 0) {
        double a = alpha_of();
        for (int i = tid; i < NEQ; i += NTHR) sx[i] = g_nu[i] + a * g_dnu[i];
    } else {
        for (int i = tid; i < NEQ; i += NTHR) sx[i] = g_dnu[i];
    }
    __syncthreads();
    for (int j = bid * 8 + warp; j < NX; j += NBLK * 8) {
        const double* ar = g_AT + (size_t)j * NEQ;
        double s = 0.0;
        for (int e = lane; e < NEQ; e += 32) s += ar[e] * sx[e];
#pragma unroll
        for (int off = 16; off; off >>= 1) s += __shfl_down_sync(0xffffffffu, s, off);
        if (lane == 0) g_t[j] = s;
    }
    __syncthreads();
}

__global__ void __launch_bounds__(NTHR, 1)
k_main(const float* __restrict__ puz, const void* __restrict__ Araw,
       const float* __restrict__ logz, float* __restrict__ out) {
    extern __shared__ double sh[];
    __shared__ double s_red[32];
    __shared__ double s_val;
    __shared__ int s_cnt;
    const int tid = threadIdx.x, bid = blockIdx.x;
    const int warp = tid >> 5, lane = tid & 31;
    unsigned tgt = 0;
    unsigned ftgt = 0;   // block 131's flag target

    // ---- dtype detect (block 0 reads first 16KB only)
    if (bid == 0) {
        if (tid == 0) s_cnt = 0;
        __syncthreads();
        int c = 0;
        const unsigned* W = (const unsigned*)Araw;
        for (int i = tid; i < 4096; i += NTHR) {
            float v = __uint_as_float(W[i]);
            if (v >= 1.0f && v < 4.0f) c++;
        }
        atomicAdd(&s_cnt, c);
        __syncthreads();
        if (tid == 0) g_is64 = (s_cnt > 64) ? 1 : 0;
    }
    gsync(tgt);

    // ---- widen A + split + init state (incl. bootstrap for fused alpha scheme)
    {
        int is64 = g_is64;
        const double* Ad = (const double*)Araw;
        const float*  Af = (const float*)Araw;
        for (size_t i = (size_t)bid * NTHR + tid; i < (size_t)NEQ * NX; i += (size_t)NBLK * NTHR) {
            double v = is64 ? Ad[i] : (double)Af[i];
            g_A[i] = v;
            float h = (float)v;
            g_Ah[i] = h;
            g_Al[i] = (float)(v - (double)h);
        }
        int i = bid * NTHR + tid;
        if (i < NX) {
            g_q[i] = -(double)puz[i];
            g_z[i] = 1.0; g_lam[i] = 1.0;
            g_w[i] = exp((double)logz[i]);
            g_dz[i] = 0.0; g_dlam[i] = 0.0;
        }
        if (i < NEQ) { g_nu[i] = 0.0; g_dnu[i] = 0.0; }
        if (bid == 0) {
            if (tid < 16) g_pmin[tid] = INFINITY;               // -> alpha = 1, updates add 0
            if (tid < 64) g_part4[tid] = ((tid & 3) == 0) ? 256.0 : 0.0;  // d1 = 4096
        }
    }
    gsync(tgt);

    // ---- transpose A -> g_AT
    {
        int tx = tid & 31, ty = tid >> 5;
        for (int t = bid; t < (NX / 32) * (NEQ / 32); t += NBLK) {
            int j0 = (t % (NX / 32)) * 32, e0 = (t / (NX / 32)) * 32;
#pragma unroll
            for (int m = 0; m < 4; m++) {
                int e = e0 + ty + 8 * m;
                sh[(ty + 8 * m) * 33 + tx] = g_A[(size_t)e * NX + j0 + tx];
            }
            __syncthreads();
#pragma unroll
            for (int m = 0; m < 4; m++) {
                int j = j0 + ty + 8 * m;
                g_AT[(size_t)j * NEQ + e0 + tx] = sh[tx * 33 + ty + 8 * m];
            }
            __syncthreads();
        }
    }
    gsync(tgt);

    // ---- b = A @ exp(log_z0)
    amv_phase(sh, 0, bid, tid, warp, lane);
    gsync(tgt);

    // =================== IPM loop ===================
    for (int it = 0; it < ITERS; it++) {
        // 1) t = A^T (nu + a*dnu)
        atmv_phase(sh, 0, bid, tid, warp, lane);
        gsync(tgt);

        // 2) pre: alpha, analytic gap, z/lam update (owners), residual vectors
        if (bid < 16) {
            double a = alpha_of();
            double d1 = 0, d2 = 0, d3 = 0, d4 = 0;
#pragma unroll
            for (int j = 0; j < 16; j++) {
                d1 += g_part4[j * 4 + 0]; d2 += g_part4[j * 4 + 1];
                d3 += g_part4[j * 4 + 2]; d4 += g_part4[j * 4 + 3];
            }
            double gap = (d1 + a * (d2 + d3) + a * a * d4) / (double)NX;
            int i = bid * NTHR + tid;
            double z  = g_z[i]   + a * g_dz[i];
            double la = g_lam[i] + a * g_dlam[i];
            g_z[i] = z; g_lam[i] = la;
            double rd = MU * z + g_q[i] - la + g_t[i];
            double rc = z * la - SIG * gap;
            double Di = 1.0 / (MU + la / z);
            double rt = -rd - rc / z;
            g_rc[i] = rc; g_Dinv[i] = Di; g_rtil[i] = rt;
            g_w[i] = rt * Di + z;
        }
        gsync(tgt);

        // 3) rhs = A@w - b ; B = fp32(A*Dinv) ; nu materialization (blocks 96..98)
        amv_phase(sh, 1, bid, tid, warp, lane);
        for (size_t i = (size_t)bid * NTHR + tid; i < (size_t)NEQ * NX; i += (size_t)NBLK * NTHR) {
            int k = (int)(i & (NX - 1));
            g_Bh[i] = (float)(g_A[i] * g_Dinv[k]);
        }
        if (bid >= 96 && bid < 99) {
            double a = alpha_of();
            int i = (bid - 96) * NTHR + tid;
            if (i < NEQ) g_nu[i] += a * g_dnu[i];
        }
        gsync(tgt);

        // 4) Gram: ADA = A D A^T (64x64 tiles); blk0: potrf panel0 + flag; blk131: M_0
        {
            const int is64 = g_is64;
            float* Ahs = (float*)sh;         // [32][68]
            float* Als = Ahs + 2176;         // is64 only
            float* Bhs = Als + 2176;
            const int txc = (tid & 15) * 4;
            const int tyr = (tid >> 4) * 4;
            for (int t = bid; t < 78; t += NBLK) {
                int bi, bj; tri_map(t, bi, bj);
                int row0 = bi * 64, col0 = bj * 64;
                float Sh_[4][4] = {{0}}, Sl_[4][4] = {{0}};
                for (int k0 = 0; k0 < NX; k0 += 32) {
                    for (int r = warp; r < 64; r += 8) {
                        size_t ga = (size_t)(row0 + r) * NX + k0 + lane;
                        size_t gb = (size_t)(col0 + r) * NX + k0 + lane;
                        Ahs[lane * 68 + r] = g_Ah[ga];
                        if (is64) Als[lane * 68 + r] = g_Al[ga];
                        Bhs[lane * 68 + r] = g_Bh[gb];
                    }
                    __syncthreads();
                    if (!is64) {
#pragma unroll
                        for (int half = 0; half < 2; half++) {
                            float acc[4][4] = {{0}};
#pragma unroll
                            for (int kk = 0; kk < 16; kk++) {
                                int k = half * 16 + kk;
                                float4 a4 = *(const float4*)(Ahs + k * 68 + tyr);
                                float4 b4 = *(const float4*)(Bhs + k * 68 + txc);
                                float av[4] = {a4.x, a4.y, a4.z, a4.w};
                                float bv[4] = {b4.x, b4.y, b4.z, b4.w};
#pragma unroll
                                for (int r = 0; r < 4; r++)
#pragma unroll
                                    for (int c = 0; c < 4; c++)
                                        acc[r][c] = __fmaf_rn(av[r], bv[c], acc[r][c]);
                            }
#pragma unroll
                            for (int r = 0; r < 4; r++)
#pragma unroll
                                for (int c = 0; c < 4; c++) {
                                    float ts = __fadd_rn(Sh_[r][c], acc[r][c]);
                                    float e  = __fadd_rn(__fsub_rn(Sh_[r][c], ts), acc[r][c]);
                                    Sh_[r][c] = ts;
                                    Sl_[r][c] = __fadd_rn(Sl_[r][c], e);
                                }
                        }
                    } else {
#pragma unroll
                        for (int half = 0; half < 2; half++) {
                            float acc[4][4] = {{0}};
                            float accl[4][4] = {{0}};
#pragma unroll
                            for (int kk = 0; kk < 16; kk++) {
                                int k = half * 16 + kk;
                                float4 a4 = *(const float4*)(Ahs + k * 68 + tyr);
                                float4 al4 = *(const float4*)(Als + k * 68 + tyr);
                                float4 b4 = *(const float4*)(Bhs + k * 68 + txc);
                                float av[4] = {a4.x, a4.y, a4.z, a4.w};
                                float alv[4] = {al4.x, al4.y, al4.z, al4.w};
                                float bv[4] = {b4.x, b4.y, b4.z, b4.w};
#pragma unroll
                                for (int r = 0; r < 4; r++)
#pragma unroll
                                    for (int c = 0; c < 4; c++) {
                                        acc[r][c]  = __fmaf_rn(av[r],  bv[c], acc[r][c]);
                                        accl[r][c] = __fmaf_rn(alv[r], bv[c], accl[r][c]);
                                    }
                            }
#pragma unroll
                            for (int r = 0; r < 4; r++)
#pragma unroll
                                for (int c = 0; c < 4; c++) {
                                    float ts = __fadd_rn(Sh_[r][c], acc[r][c]);
                                    float e  = __fadd_rn(__fsub_rn(Sh_[r][c], ts), acc[r][c]);
                                    Sh_[r][c] = ts;
                                    Sl_[r][c] = __fadd_rn(Sl_[r][c], __fadd_rn(e, accl[r][c]));
                                }
                        }
                    }
                    __syncthreads();
                }
#pragma unroll
                for (int r = 0; r < 4; r++)
#pragma unroll
                    for (int c = 0; c < 4; c++)
                        g_ADA[(size_t)(row0 + tyr + r) * NEQ + col0 + txc + c] =
                            (double)Sh_[r][c] + (double)Sl_[r][c];
            }
            if (bid == 0) {
                __syncthreads();
                potrf_panel(sh, 0, tid);
                __syncthreads();
                if (tid == 0) { __threadfence(); atomicAdd(&g_flag, 1u); }
            }
            if (bid == NBLK - 1) {
                flag_wait(++ftgt);
                msweep(sh, 0, tid);
            }
        }
        gsync(tgt);

        // 5) Cholesky panels: [trsm-GEMM] ; [syrk + blk0 potrf_{p+1}+flag + blk131 M_{p+1}]
        for (int p = 0; p < 12; p++) {
            int o = p * 64, rem = NEQ - o - 64;

            // trsm as dense GEMM: X = A21 * M_p  (bar-free, fully parallel)
            if (rem > 0 && bid < rem / 64) {
                double* As = sh;          // [64][65] A21 rows
                double* Ms = sh + 4160;   // [64][65] M_p
                int base = o + 64 + bid * 64;
                for (int i = tid; i < 4096; i += NTHR) {
                    int r = i >> 6, c = i & 63;
                    As[r * 65 + c] = g_ADA[(size_t)(base + r) * NEQ + o + c];
                    Ms[r * 65 + c] = g_W[(size_t)p * 4096 + i];
                }
                __syncthreads();
                const int tyr = (tid >> 4) * 4;
                const int txc = (tid & 15) * 4;
                double acc[4][4] = {{0}};
#pragma unroll 4
                for (int k = 0; k < 64; k++) {
                    double m0 = Ms[k * 65 + txc], m1 = Ms[k * 65 + txc + 1];
                    double m2 = Ms[k * 65 + txc + 2], m3 = Ms[k * 65 + txc + 3];
#pragma unroll
                    for (int r = 0; r < 4; r++) {
                        double av = As[(tyr + r) * 65 + k];
                        acc[r][0] = __fma_rn(av, m0, acc[r][0]);
                        acc[r][1] = __fma_rn(av, m1, acc[r][1]);
                        acc[r][2] = __fma_rn(av, m2, acc[r][2]);
                        acc[r][3] = __fma_rn(av, m3, acc[r][3]);
                    }
                }
#pragma unroll
                for (int r = 0; r < 4; r++)
#pragma unroll
                    for (int c = 0; c < 4; c++)
                        g_ADA[(size_t)(base + tyr + r) * NEQ + o + txc + c] = acc[r][c];
            }
            gsync(tgt);

            // syrk + lookahead potrf + M-sweep
            if (rem > 0) {
                int nb = rem / 64, nt = nb * (nb + 1) / 2;
                float* Ahs = (float*)sh;       // [32][68]
                float* Als = Ahs + 2176;
                float* Bhs = Als + 2176;
                float* Bls = Bhs + 2176;
                const int txc = (tid & 15) * 4;
                const int tyr = (tid >> 4) * 4;
                int o2 = o + 64;
                for (int t = bid; t < nt; t += NBLK) {
                    int bi, bj; tri_map(t, bi, bj);
                    int r0 = o2 + bi * 64, c0 = o2 + bj * 64;
                    float Hh[4][4] = {{0}}, Hl[4][4] = {{0}};
                    for (int kq = 0; kq < 64; kq += 32) {
                        for (int r = warp; r < 64; r += 8) {
                            double va = g_ADA[(size_t)(r0 + r) * NEQ + o + kq + lane];
                            double vb = g_ADA[(size_t)(c0 + r) * NEQ + o + kq + lane];
                            float ha = (float)va, hb = (float)vb;
                            Ahs[lane * 68 + r] = ha;
                            Als[lane * 68 + r] = (float)(va - (double)ha);
                            Bhs[lane * 68 + r] = hb;
                            Bls[lane * 68 + r] = (float)(vb - (double)hb);
                        }
                        __syncthreads();
#pragma unroll 4
                        for (int k = 0; k < 32; k++) {
                            float4 a4 = *(const float4*)(Ahs + k * 68 + tyr);
                            float4 al4 = *(const float4*)(Als + k * 68 + tyr);
                            float4 bh4 = *(const float4*)(Bhs + k * 68 + txc);
                            float4 bl4 = *(const float4*)(Bls + k * 68 + txc);
                            float av[4] = {a4.x, a4.y, a4.z, a4.w};
                            float alv[4] = {al4.x, al4.y, al4.z, al4.w};
                            float bh[4] = {bh4.x, bh4.y, bh4.z, bh4.w};
                            float bl[4] = {bl4.x, bl4.y, bl4.z, bl4.w};
#pragma unroll
                            for (int r = 0; r < 4; r++)
#pragma unroll
                                for (int c = 0; c < 4; c++) {
                                    float pf = __fmul_rn(av[r], bh[c]);
                                    float e = __fmaf_rn(av[r], bh[c], -pf);
                                    e = __fmaf_rn(av[r], bl[c], e);
                                    e = __fmaf_rn(alv[r], bh[c], e);
                                    float s = __fadd_rn(Hh[r][c], pf);
                                    float bb = __fsub_rn(s, Hh[r][c]);
                                    float err = __fadd_rn(__fsub_rn(Hh[r][c], __fsub_rn(s, bb)),
                                                          __fsub_rn(pf, bb));
                                    Hh[r][c] = s;
                                    Hl[r][c] = __fadd_rn(Hl[r][c], __fadd_rn(e, err));
                                }
                        }
                        __syncthreads();
                    }
#pragma unroll
                    for (int r = 0; r < 4; r++)
#pragma unroll
                        for (int c = 0; c < 4; c++)
                            g_ADA[(size_t)(r0 + tyr + r) * NEQ + c0 + txc + c] -=
                                ((double)Hh[r][c] + (double)Hl[r][c]);
                }
                // lookahead: block 0 factors panel p+1 (its tile t=0 was the diag tile)
                if (bid == 0) {
                    __syncthreads();
                    potrf_panel(sh, o2, tid);
                    __syncthreads();
                    if (tid == 0) { __threadfence(); atomicAdd(&g_flag, 1u); }
                }
                if (bid == NBLK - 1) {
                    flag_wait(++ftgt);
                    msweep(sh, p + 1, tid);
                }
                gsync(tgt);
            }
        }

        // 6) triangular solves (block 0): diag via M_p matvecs + bulk updates
        if (bid == 0) {
            double* y   = sh;            // [768]
            double* Wm  = sh + 768;      // [64][65]
            double* tmp = sh + 4928;     // [4][64]
            for (int i = tid; i < NEQ; i += NTHR) y[i] = g_rhs[i];
            __syncthreads();
            int r = tid & 63, qg = tid >> 6;
            for (int p = 0; p < 12; p++) {
                int o = p * 64;
                for (int i = tid; i < 4096; i += NTHR)
                    Wm[(i >> 6) * 65 + (i & 63)] = g_W[(size_t)p * 4096 + i];
                __syncthreads();
                double s = 0.0;
                for (int j = qg; j < 64; j += 4) s += Wm[j * 65 + r] * y[o + j];
                tmp[qg * 64 + r] = s;
                __syncthreads();
                if (tid < 64)
                    y[o + tid] = tmp[tid] + tmp[64 + tid] + tmp[128 + tid] + tmp[192 + tid];
                __syncthreads();
                for (int rr = o + 64 + warp; rr < NEQ; rr += 8) {
                    double s2 = 0.0;
#pragma unroll
                    for (int k = lane; k < 64; k += 32) s2 += g_ADA[(size_t)rr * NEQ + o + k] * y[o + k];
#pragma unroll
                    for (int off = 16; off; off >>= 1) s2 += __shfl_down_sync(0xffffffffu, s2, off);
                    if (lane == 0) y[rr] -= s2;
                }
                __syncthreads();
            }
            for (int p = 11; p >= 0; p--) {
                int o = p * 64;
                for (int i = tid; i < 4096; i += NTHR)
                    Wm[(i >> 6) * 65 + (i & 63)] = g_W[(size_t)p * 4096 + i];
                __syncthreads();
                double s = 0.0;
                for (int j = qg; j < 64; j += 4) s += Wm[r * 65 + j] * y[o + j];
                tmp[qg * 64 + r] = s;
                __syncthreads();
                if (tid < 64)
                    y[o + tid] = tmp[tid] + tmp[64 + tid] + tmp[128 + tid] + tmp[192 + tid];
                __syncthreads();
                for (int i = tid; i < o; i += NTHR) {
                    double s2 = 0.0;
#pragma unroll 8
                    for (int jj = 0; jj < 64; jj++) s2 += g_ADA[(size_t)(o + jj) * NEQ + i] * y[o + jj];
                    y[i] -= s2;
                }
                __syncthreads();
            }
            for (int i = tid; i < NEQ; i += NTHR) g_dnu[i] = y[i];
        }
        gsync(tgt);

        // 7) t = A^T dnu
        atmv_phase(sh, 1, bid, tid, warp, lane);
        gsync(tgt);

        // 8) stepA: dz, dlam, fraction-min partials, 4 dot partials (for next gap)
        if (bid < 16) {
            int i = bid * NTHR + tid;
            double rt = g_rtil[i], t2 = g_t[i], Di = g_Dinv[i];
            double rc = g_rc[i], la = g_lam[i], zz = g_z[i];
            double dz = (rt - t2) * Di;
            double dl = (-rc - la * dz) / zz;
            g_dz[i] = dz; g_dlam[i] = dl;
            double mn = INFINITY;
            if (dz < 0.0) mn = fmin(mn, -zz / dz);
            if (dl < 0.0) mn = fmin(mn, -la / dl);
            blk_min_to(mn, s_red, tid, &s_val);
            if (tid == 0) g_pmin[bid] = s_val;
            __syncthreads();
            blk_sum4_to(zz * la, zz * dl, dz * la, dz * dl, s_red, tid, bid);
        }
        gsync(tgt);
    }

    // ---- output: z_final = z + alpha_last * dz
    if (bid < 16) {
        double a = alpha_of();
        int i = bid * NTHR + tid;
        out[i] = (float)(g_z[i] + a * g_dz[i]);
    }
}

// ---------------- host launcher (2 graph nodes) ----------------
extern "C" void kernel_launch(void* const* d_in, const int* in_sizes, int n_in,
                              void* d_out, int out_size) {
    const float* puz  = (const float*)d_in[0];
    const void*  Araw = d_in[1];
    const float* logz = (const float*)d_in[2];
    float* out = (float*)d_out;

    static int attr_set = 0;
    if (!attr_set) {
        cudaFuncSetAttribute(k_main, cudaFuncAttributeMaxDynamicSharedMemorySize,
                             SMEM_DBL * (int)sizeof(double));
        attr_set = 1;
    }

    k_reset<<<1, 1>>>();
    k_main<<<NBLK, NTHR, SMEM_DBL * sizeof(double)>>>(puz, Araw, logz, out);
}

// round 17
// speedup vs baseline: 1.1556x; 1.1556x over previous
#include <cuda_runtime.h>
#include <math.h>

#define NX    4096
#define NEQ   768
#define MU    0.1
#define SIG   0.1
#define ITERS 40
#define NBLK  132
#define NTHR  256
#define SMEM_DBL 8320          // 66560 bytes dynamic shared

// ---------------- device-global state ----------------
__device__ double g_A[(size_t)NEQ * NX];
__device__ double g_AT[(size_t)NX * NEQ];
__device__ float  g_Ah[(size_t)NEQ * NX];
__device__ float  g_Al[(size_t)NEQ * NX];
__device__ float  g_Bh[(size_t)NEQ * NX];   // (A * Dinv) rounded to fp32
__device__ double g_q[NX];
__device__ double g_b[NEQ];
__device__ double g_z[NX];
__device__ double g_lam[NX];
__device__ double g_nu[NEQ];
__device__ double g_t[NX];
__device__ double g_rc[NX];
__device__ double g_Dinv[NX];
__device__ double g_rtil[NX];
__device__ double g_w[NX];
__device__ double g_dnu[NEQ];
__device__ double g_rhs[NEQ];
__device__ double g_ADA[NEQ * NEQ];
__device__ double g_invd[NEQ];           // 1/L[j][j]
__device__ double g_W[12 * 64 * 64];     // M_p = inv(L_pp)^T, row-major 64x64 per panel
__device__ double g_dz[NX];
__device__ double g_dlam[NX];
__device__ double g_part4[16 * 4];       // per-block partials of {z.lam, z.dlam, dz.lam, dz.dlam}
__device__ double g_pmin[16];
__device__ int    g_is64;
__device__ unsigned g_count;
__device__ unsigned g_flag;              // potrf-completion flag (monotonic)

__global__ void k_reset() { g_count = 0u; g_flag = 0u; }

// software grid barrier: arrive with atomic, poll with plain L2 load
__device__ __forceinline__ void gsync(unsigned &tgt) {
    __syncthreads();
    if (threadIdx.x == 0) {
        __threadfence();
        atomicAdd(&g_count, 1u);
        tgt += NBLK;
        while (*(volatile unsigned*)&g_count < tgt) __nanosleep(32);
        __threadfence();
    }
    __syncthreads();
}

// block 131 waits until g_flag >= tgt (release by block 0 after potrf)
__device__ __forceinline__ void flag_wait(unsigned tgt) {
    __syncthreads();
    if (threadIdx.x == 0) {
        while (*(volatile unsigned*)&g_flag < tgt) __nanosleep(32);
        __threadfence();
    }
    __syncthreads();
}

__device__ __forceinline__ double alpha_of() {
    double a = g_pmin[0];
#pragma unroll
    for (int j = 1; j < 16; j++) a = fmin(a, g_pmin[j]);
    return fmin(1.0, 0.99 * a);
}

__device__ __forceinline__ void blk_min_to(double v, double* s_red, int tid, double* dst) {
#pragma unroll
    for (int off = 16; off; off >>= 1) v = fmin(v, __shfl_down_sync(0xffffffffu, v, off));
    if ((tid & 31) == 0) s_red[tid >> 5] = v;
    __syncthreads();
    if (tid == 0) { double r = s_red[0]; for (int w = 1; w < 8; w++) r = fmin(r, s_red[w]); *dst = r; }
    __syncthreads();
}

// 4 simultaneous deterministic block sums -> g_part4[bid]
__device__ __forceinline__ void blk_sum4_to(double v0, double v1, double v2, double v3,
                                            double* s4, int tid, int bid) {
#pragma unroll
    for (int off = 16; off; off >>= 1) {
        v0 += __shfl_down_sync(0xffffffffu, v0, off);
        v1 += __shfl_down_sync(0xffffffffu, v1, off);
        v2 += __shfl_down_sync(0xffffffffu, v2, off);
        v3 += __shfl_down_sync(0xffffffffu, v3, off);
    }
    if ((tid & 31) == 0) {
        int w = tid >> 5;
        s4[w * 4 + 0] = v0; s4[w * 4 + 1] = v1; s4[w * 4 + 2] = v2; s4[w * 4 + 3] = v3;
    }
    __syncthreads();
    if (tid == 0) {
        double a0 = 0, a1 = 0, a2 = 0, a3 = 0;
        for (int w = 0; w < 8; w++) {
            a0 += s4[w * 4]; a1 += s4[w * 4 + 1]; a2 += s4[w * 4 + 2]; a3 += s4[w * 4 + 3];
        }
        g_part4[bid * 4 + 0] = a0; g_part4[bid * 4 + 1] = a1;
        g_part4[bid * 4 + 2] = a2; g_part4[bid * 4 + 3] = a3;
    }
    __syncthreads();
}

__device__ __forceinline__ void tri_map(int t, int &bi, int &bj) {
    int b = 0;
    while ((b + 1) * (b + 2) / 2 <= t) b++;
    bi = b; bj = t - b * (b + 1) / 2;
}

// range-safe fp64 reciprocal: integer magic seed + 4 fused Newton steps
__device__ __forceinline__ double fast_rcp(double d) {
    double r = __longlong_as_double(0x7FDE6238502484BAll - __double_as_longlong(d));
#pragma unroll
    for (int s = 0; s < 4; s++) {
        double e = __fma_rn(-d, r, 1.0);
        r = __fma_rn(r, e, r);
    }
    return r;
}

// potrf of 64x64 diagonal block at offset o (one block, 256 threads).
__device__ void potrf_panel(double* sh, int o, int tid) {
    double* S   = sh;            // [64][65]
    double* wv  = sh + 4160;
    double* inv = sh + 4224;
    double* rsv = sh + 4288;
    for (int i = tid; i < 4096; i += NTHR) {
        int r = i >> 6, c = i & 63;
        S[r * 65 + c] = g_ADA[(size_t)(o + r) * NEQ + o + c];
    }
    __syncthreads();
    int r = tid & 63, q = tid >> 6;
    for (int j = 0; j < 64; j++) {
        if (q == 0) {
            double d = fmax(S[j * 65 + j], 1e-300);
            double ri = fast_rcp(d);
            if (r == j) inv[j] = ri;
            if (r > j) wv[r] = S[r * 65 + j] * ri;
        }
        __syncthreads();
        if (r > j) {
            double wr = wv[r];
            for (int c = j + 1 + q; c <= r; c += 4)
                S[r * 65 + c] -= wr * S[c * 65 + j];
        }
        __syncthreads();
    }
    if (tid < 64) {
        double rs = sqrt(inv[tid]);
        rsv[tid] = rs;
        g_invd[o + tid] = rs;
    }
    __syncthreads();
    for (int i = tid; i < 4096; i += NTHR) {
        int rr = i >> 6, c = i & 63;
        g_ADA[(size_t)(o + rr) * NEQ + o + c] = S[rr * 65 + c] * rsv[c];
    }
}

// M_p = inv(L_pp)^T via identity column sweep (one block). Writes g_W[p].
__device__ void msweep(double* sh, int p, int tid) {
    int o = p * 64;
    double* L = sh;          // [64][65]
    double* X = sh + 4160;   // [64][65]
    for (int i = tid; i < 4096; i += NTHR) {
        int r = i >> 6, c = i & 63;
        L[r * 65 + c] = g_ADA[(size_t)(o + r) * NEQ + o + c];
        X[r * 65 + c] = (r == c) ? 1.0 : 0.0;
    }
    __syncthreads();
    if (tid < 64) L[tid * 65 + tid] = g_invd[o + tid];
    __syncthreads();
    int r = tid & 63, q = tid >> 6;
    for (int j = 0; j < 64; j++) {
        if (q == 0) X[r * 65 + j] *= L[j * 65 + j];
        __syncthreads();
        double xj = X[r * 65 + j];
        for (int c = j + 1 + q; c < 64; c += 4)
            X[r * 65 + c] -= xj * L[c * 65 + j];
        __syncthreads();
    }
    for (int i = tid; i < 4096; i += NTHR) {
        int rr = i >> 6, c = i & 63;
        g_W[(size_t)p * 4096 + rr * 64 + c] = X[rr * 65 + c];
    }
}

// A @ w  (mode 0 -> g_b ; mode 1 -> g_rhs = A@w - b)
__device__ __forceinline__ void amv_phase(double* sv, int mode, int bid, int tid, int warp, int lane) {
    for (int i = tid; i < NX; i += NTHR) sv[i] = g_w[i];
    __syncthreads();
    int row = bid * 8 + warp;
    if (row < NEQ) {
        const double* ar = g_A + (size_t)row * NX;
        double s = 0.0;
        for (int k = lane; k < NX; k += 32) s += ar[k] * sv[k];
#pragma unroll
        for (int off = 16; off; off >>= 1) s += __shfl_down_sync(0xffffffffu, s, off);
        if (lane == 0) { if (mode == 0) g_b[row] = s; else g_rhs[row] = s - g_b[row]; }
    }
    __syncthreads();
}

// g_t = A^T @ x; mode 0: x = nu + alpha*dnu (on-the-fly); mode 1: x = dnu
__device__ __forceinline__ void atmv_phase(double* sx, int mode, int bid, int tid, int warp, int lane) {
    if (mode == 0) {
        double a = alpha_of();
        for (int i = tid; i < NEQ; i += NTHR) sx[i] = g_nu[i] + a * g_dnu[i];
    } else {
        for (int i = tid; i < NEQ; i += NTHR) sx[i] = g_dnu[i];
    }
    __syncthreads();
    for (int j = bid * 8 + warp; j < NX; j += NBLK * 8) {
        const double* ar = g_AT + (size_t)j * NEQ;
        double s = 0.0;
        for (int e = lane; e < NEQ; e += 32) s += ar[e] * sx[e];
#pragma unroll
        for (int off = 16; off; off >>= 1) s += __shfl_down_sync(0xffffffffu, s, off);
        if (lane == 0) g_t[j] = s;
    }
    __syncthreads();
}

__global__ void __launch_bounds__(NTHR, 1)
k_main(const float* __restrict__ puz, const void* __restrict__ Araw,
       const float* __restrict__ logz, float* __restrict__ out) {
    extern __shared__ double sh[];
    __shared__ double s_red[32];
    __shared__ double s_val;
    __shared__ int s_cnt;
    const int tid = threadIdx.x, bid = blockIdx.x;
    const int warp = tid >> 5, lane = tid & 31;
    unsigned tgt = 0;
    unsigned ftgt = 0;   // block 131's flag target

    // ---- dtype detect (block 0 reads first 16KB only)
    if (bid == 0) {
        if (tid == 0) s_cnt = 0;
        __syncthreads();
        int c = 0;
        const unsigned* W = (const unsigned*)Araw;
        for (int i = tid; i < 4096; i += NTHR) {
            float v = __uint_as_float(W[i]);
            if (v >= 1.0f && v < 4.0f) c++;
        }
        atomicAdd(&s_cnt, c);
        __syncthreads();
        if (tid == 0) g_is64 = (s_cnt > 64) ? 1 : 0;
    }
    gsync(tgt);

    // ---- widen A + split + init state (incl. bootstrap for fused alpha scheme)
    {
        int is64 = g_is64;
        const double* Ad = (const double*)Araw;
        const float*  Af = (const float*)Araw;
        for (size_t i = (size_t)bid * NTHR + tid; i < (size_t)NEQ * NX; i += (size_t)NBLK * NTHR) {
            double v = is64 ? Ad[i] : (double)Af[i];
            g_A[i] = v;
            float h = (float)v;
            g_Ah[i] = h;
            g_Al[i] = (float)(v - (double)h);
        }
        int i = bid * NTHR + tid;
        if (i < NX) {
            g_q[i] = -(double)puz[i];
            g_z[i] = 1.0; g_lam[i] = 1.0;
            g_w[i] = exp((double)logz[i]);
            g_dz[i] = 0.0; g_dlam[i] = 0.0;
        }
        if (i < NEQ) { g_nu[i] = 0.0; g_dnu[i] = 0.0; }
        if (bid == 0) {
            if (tid < 16) g_pmin[tid] = INFINITY;               // -> alpha = 1, updates add 0
            if (tid < 64) g_part4[tid] = ((tid & 3) == 0) ? 256.0 : 0.0;  // d1 = 4096
        }
    }
    gsync(tgt);

    // ---- transpose A -> g_AT
    {
        int tx = tid & 31, ty = tid >> 5;
        for (int t = bid; t < (NX / 32) * (NEQ / 32); t += NBLK) {
            int j0 = (t % (NX / 32)) * 32, e0 = (t / (NX / 32)) * 32;
#pragma unroll
            for (int m = 0; m < 4; m++) {
                int e = e0 + ty + 8 * m;
                sh[(ty + 8 * m) * 33 + tx] = g_A[(size_t)e * NX + j0 + tx];
            }
            __syncthreads();
#pragma unroll
            for (int m = 0; m < 4; m++) {
                int j = j0 + ty + 8 * m;
                g_AT[(size_t)j * NEQ + e0 + tx] = sh[tx * 33 + ty + 8 * m];
            }
            __syncthreads();
        }
    }
    gsync(tgt);

    // ---- b = A @ exp(log_z0)
    amv_phase(sh, 0, bid, tid, warp, lane);
    gsync(tgt);

    // =================== IPM loop ===================
    for (int it = 0; it < ITERS; it++) {
        // 1) t = A^T (nu + a*dnu)
        atmv_phase(sh, 0, bid, tid, warp, lane);
        gsync(tgt);

        // 2) pre: alpha, analytic gap, z/lam update (owners), residual vectors
        if (bid < 16) {
            double a = alpha_of();
            double d1 = 0, d2 = 0, d3 = 0, d4 = 0;
#pragma unroll
            for (int j = 0; j < 16; j++) {
                d1 += g_part4[j * 4 + 0]; d2 += g_part4[j * 4 + 1];
                d3 += g_part4[j * 4 + 2]; d4 += g_part4[j * 4 + 3];
            }
            double gap = (d1 + a * (d2 + d3) + a * a * d4) / (double)NX;
            int i = bid * NTHR + tid;
            double z  = g_z[i]   + a * g_dz[i];
            double la = g_lam[i] + a * g_dlam[i];
            g_z[i] = z; g_lam[i] = la;
            double rd = MU * z + g_q[i] - la + g_t[i];
            double rc = z * la - SIG * gap;
            double Di = 1.0 / (MU + la / z);
            double rt = -rd - rc / z;
            g_rc[i] = rc; g_Dinv[i] = Di; g_rtil[i] = rt;
            g_w[i] = rt * Di + z;
        }
        gsync(tgt);

        // 3) rhs = A@w - b ; B = fp32(A*Dinv) ; nu materialization (blocks 96..98)
        amv_phase(sh, 1, bid, tid, warp, lane);
        for (size_t i = (size_t)bid * NTHR + tid; i < (size_t)NEQ * NX; i += (size_t)NBLK * NTHR) {
            int k = (int)(i & (NX - 1));
            g_Bh[i] = (float)(g_A[i] * g_Dinv[k]);
        }
        if (bid >= 96 && bid < 99) {
            double a = alpha_of();
            int i = (bid - 96) * NTHR + tid;
            if (i < NEQ) g_nu[i] += a * g_dnu[i];
        }
        gsync(tgt);

        // 4) Gram: ADA = A D A^T (64x64 tiles); blk0: potrf panel0 + flag; blk131: M_0
        {
            const int is64 = g_is64;
            float* Ahs = (float*)sh;         // [32][68]
            float* Als = Ahs + 2176;         // is64 only
            float* Bhs = Als + 2176;
            const int txc = (tid & 15) * 4;
            const int tyr = (tid >> 4) * 4;
            for (int t = bid; t < 78; t += NBLK) {
                int bi, bj; tri_map(t, bi, bj);
                int row0 = bi * 64, col0 = bj * 64;
                float Sh_[4][4] = {{0}}, Sl_[4][4] = {{0}};
                for (int k0 = 0; k0 < NX; k0 += 32) {
                    for (int r = warp; r < 64; r += 8) {
                        size_t ga = (size_t)(row0 + r) * NX + k0 + lane;
                        size_t gb = (size_t)(col0 + r) * NX + k0 + lane;
                        Ahs[lane * 68 + r] = g_Ah[ga];
                        if (is64) Als[lane * 68 + r] = g_Al[ga];
                        Bhs[lane * 68 + r] = g_Bh[gb];
                    }
                    __syncthreads();
                    if (!is64) {
#pragma unroll
                        for (int half = 0; half < 2; half++) {
                            float acc[4][4] = {{0}};
#pragma unroll
                            for (int kk = 0; kk < 16; kk++) {
                                int k = half * 16 + kk;
                                float4 a4 = *(const float4*)(Ahs + k * 68 + tyr);
                                float4 b4 = *(const float4*)(Bhs + k * 68 + txc);
                                float av[4] = {a4.x, a4.y, a4.z, a4.w};
                                float bv[4] = {b4.x, b4.y, b4.z, b4.w};
#pragma unroll
                                for (int r = 0; r < 4; r++)
#pragma unroll
                                    for (int c = 0; c < 4; c++)
                                        acc[r][c] = __fmaf_rn(av[r], bv[c], acc[r][c]);
                            }
#pragma unroll
                            for (int r = 0; r < 4; r++)
#pragma unroll
                                for (int c = 0; c < 4; c++) {
                                    float ts = __fadd_rn(Sh_[r][c], acc[r][c]);
                                    float e  = __fadd_rn(__fsub_rn(Sh_[r][c], ts), acc[r][c]);
                                    Sh_[r][c] = ts;
                                    Sl_[r][c] = __fadd_rn(Sl_[r][c], e);
                                }
                        }
                    } else {
#pragma unroll
                        for (int half = 0; half < 2; half++) {
                            float acc[4][4] = {{0}};
                            float accl[4][4] = {{0}};
#pragma unroll
                            for (int kk = 0; kk < 16; kk++) {
                                int k = half * 16 + kk;
                                float4 a4 = *(const float4*)(Ahs + k * 68 + tyr);
                                float4 al4 = *(const float4*)(Als + k * 68 + tyr);
                                float4 b4 = *(const float4*)(Bhs + k * 68 + txc);
                                float av[4] = {a4.x, a4.y, a4.z, a4.w};
                                float alv[4] = {al4.x, al4.y, al4.z, al4.w};
                                float bv[4] = {b4.x, b4.y, b4.z, b4.w};
#pragma unroll
                                for (int r = 0; r < 4; r++)
#pragma unroll
                                    for (int c = 0; c < 4; c++) {
                                        acc[r][c]  = __fmaf_rn(av[r],  bv[c], acc[r][c]);
                                        accl[r][c] = __fmaf_rn(alv[r], bv[c], accl[r][c]);
                                    }
                            }
#pragma unroll
                            for (int r = 0; r < 4; r++)
#pragma unroll
                                for (int c = 0; c < 4; c++) {
                                    float ts = __fadd_rn(Sh_[r][c], acc[r][c]);
                                    float e  = __fadd_rn(__fsub_rn(Sh_[r][c], ts), acc[r][c]);
                                    Sh_[r][c] = ts;
                                    Sl_[r][c] = __fadd_rn(Sl_[r][c], __fadd_rn(e, accl[r][c]));
                                }
                        }
                    }
                    __syncthreads();
                }
#pragma unroll
                for (int r = 0; r < 4; r++)
#pragma unroll
                    for (int c = 0; c < 4; c++)
                        g_ADA[(size_t)(row0 + tyr + r) * NEQ + col0 + txc + c] =
                            (double)Sh_[r][c] + (double)Sl_[r][c];
            }
            if (bid == 0) {
                __syncthreads();
                potrf_panel(sh, 0, tid);
                __syncthreads();
                if (tid == 0) { __threadfence(); atomicAdd(&g_flag, 1u); }
            }
            if (bid == NBLK - 1) {
                flag_wait(++ftgt);
                msweep(sh, 0, tid);
            }
        }
        gsync(tgt);

        // 5) Cholesky panels: [trsm fp32-split GEMM] ; [syrk + potrf_{p+1} + M_{p+1}]
        for (int p = 0; p < 12; p++) {
            int o = p * 64, rem = NEQ - o - 64;

            // trsm: X = A21 * M_p as fp32-split knuth GEMM (bar-light, FFMA pipe)
            if (rem > 0 && bid < rem / 64) {
                float* Ah_ = (float*)sh;        // [32][68] A21 chunk (k-major)
                float* Al_ = Ah_ + 2176;
                float* Mh_ = Al_ + 2176;        // [32][68] M_p chunk (k-major)
                float* Ml_ = Mh_ + 2176;
                int base = o + 64 + bid * 64;
                const int tyr = (tid >> 4) * 4;
                const int txc = (tid & 15) * 4;
                float Hh[4][4] = {{0}}, Hl[4][4] = {{0}};
                for (int kq = 0; kq < 64; kq += 32) {
                    // A21: lane = k (coalesced 256B rows of g_ADA)
                    for (int r = warp; r < 64; r += 8) {
                        double va = g_ADA[(size_t)(base + r) * NEQ + o + kq + lane];
                        float ha = (float)va;
                        Ah_[lane * 68 + r] = ha;
                        Al_[lane * 68 + r] = (float)(va - (double)ha);
                    }
                    // M_p: lane = column (coalesced rows of g_W)
                    for (int kk = warp; kk < 32; kk += 8) {
#pragma unroll
                        for (int ch = 0; ch < 2; ch++) {
                            int c = ch * 32 + lane;
                            double vm = g_W[(size_t)p * 4096 + (size_t)(kq + kk) * 64 + c];
                            float hm = (float)vm;
                            Mh_[kk * 68 + c] = hm;
                            Ml_[kk * 68 + c] = (float)(vm - (double)hm);
                        }
                    }
                    __syncthreads();
#pragma unroll 4
                    for (int k = 0; k < 32; k++) {
                        float4 a4 = *(const float4*)(Ah_ + k * 68 + tyr);
                        float4 al4 = *(const float4*)(Al_ + k * 68 + tyr);
                        float4 mh4 = *(const float4*)(Mh_ + k * 68 + txc);
                        float4 ml4 = *(const float4*)(Ml_ + k * 68 + txc);
                        float av[4] = {a4.x, a4.y, a4.z, a4.w};
                        float alv[4] = {al4.x, al4.y, al4.z, al4.w};
                        float mh[4] = {mh4.x, mh4.y, mh4.z, mh4.w};
                        float ml[4] = {ml4.x, ml4.y, ml4.z, ml4.w};
#pragma unroll
                        for (int r = 0; r < 4; r++)
#pragma unroll
                            for (int c = 0; c < 4; c++) {
                                float pf = __fmul_rn(av[r], mh[c]);
                                float e = __fmaf_rn(av[r], mh[c], -pf);
                                e = __fmaf_rn(av[r], ml[c], e);
                                e = __fmaf_rn(alv[r], mh[c], e);
                                float s = __fadd_rn(Hh[r][c], pf);
                                float bb = __fsub_rn(s, Hh[r][c]);
                                float err = __fadd_rn(__fsub_rn(Hh[r][c], __fsub_rn(s, bb)),
                                                      __fsub_rn(pf, bb));
                                Hh[r][c] = s;
                                Hl[r][c] = __fadd_rn(Hl[r][c], __fadd_rn(e, err));
                            }
                    }
                    __syncthreads();
                }
#pragma unroll
                for (int r = 0; r < 4; r++)
#pragma unroll
                    for (int c = 0; c < 4; c++)
                        g_ADA[(size_t)(base + tyr + r) * NEQ + o + txc + c] =
                            (double)Hh[r][c] + (double)Hl[r][c];
            }
            gsync(tgt);

            // syrk + lookahead potrf + M-sweep
            if (rem > 0) {
                int nb = rem / 64, nt = nb * (nb + 1) / 2;
                float* Ahs = (float*)sh;       // [32][68]
                float* Als = Ahs + 2176;
                float* Bhs = Als + 2176;
                float* Bls = Bhs + 2176;
                const int txc = (tid & 15) * 4;
                const int tyr = (tid >> 4) * 4;
                int o2 = o + 64;
                for (int t = bid; t < nt; t += NBLK) {
                    int bi, bj; tri_map(t, bi, bj);
                    int r0 = o2 + bi * 64, c0 = o2 + bj * 64;
                    float Hh[4][4] = {{0}}, Hl[4][4] = {{0}};
                    for (int kq = 0; kq < 64; kq += 32) {
                        for (int r = warp; r < 64; r += 8) {
                            double va = g_ADA[(size_t)(r0 + r) * NEQ + o + kq + lane];
                            double vb = g_ADA[(size_t)(c0 + r) * NEQ + o + kq + lane];
                            float ha = (float)va, hb = (float)vb;
                            Ahs[lane * 68 + r] = ha;
                            Als[lane * 68 + r] = (float)(va - (double)ha);
                            Bhs[lane * 68 + r] = hb;
                            Bls[lane * 68 + r] = (float)(vb - (double)hb);
                        }
                        __syncthreads();
#pragma unroll 4
                        for (int k = 0; k < 32; k++) {
                            float4 a4 = *(const float4*)(Ahs + k * 68 + tyr);
                            float4 al4 = *(const float4*)(Als + k * 68 + tyr);
                            float4 bh4 = *(const float4*)(Bhs + k * 68 + txc);
                            float4 bl4 = *(const float4*)(Bls + k * 68 + txc);
                            float av[4] = {a4.x, a4.y, a4.z, a4.w};
                            float alv[4] = {al4.x, al4.y, al4.z, al4.w};
                            float bh[4] = {bh4.x, bh4.y, bh4.z, bh4.w};
                            float bl[4] = {bl4.x, bl4.y, bl4.z, bl4.w};
#pragma unroll
                            for (int r = 0; r < 4; r++)
#pragma unroll
                                for (int c = 0; c < 4; c++) {
                                    float pf = __fmul_rn(av[r], bh[c]);
                                    float e = __fmaf_rn(av[r], bh[c], -pf);
                                    e = __fmaf_rn(av[r], bl[c], e);
                                    e = __fmaf_rn(alv[r], bh[c], e);
                                    float s = __fadd_rn(Hh[r][c], pf);
                                    float bb = __fsub_rn(s, Hh[r][c]);
                                    float err = __fadd_rn(__fsub_rn(Hh[r][c], __fsub_rn(s, bb)),
                                                          __fsub_rn(pf, bb));
                                    Hh[r][c] = s;
                                    Hl[r][c] = __fadd_rn(Hl[r][c], __fadd_rn(e, err));
                                }
                        }
                        __syncthreads();
                    }
#pragma unroll
                    for (int r = 0; r < 4; r++)
#pragma unroll
                        for (int c = 0; c < 4; c++)
                            g_ADA[(size_t)(r0 + tyr + r) * NEQ + c0 + txc + c] -=
                                ((double)Hh[r][c] + (double)Hl[r][c]);
                }
                // lookahead: block 0 factors panel p+1 (its tile t=0 was the diag tile)
                if (bid == 0) {
                    __syncthreads();
                    potrf_panel(sh, o2, tid);
                    __syncthreads();
                    if (tid == 0) { __threadfence(); atomicAdd(&g_flag, 1u); }
                }
                if (bid == NBLK - 1) {
                    flag_wait(++ftgt);
                    msweep(sh, p + 1, tid);
                }
                gsync(tgt);
            }
        }

        // 6) triangular solves (block 0): diag via M_p matvecs + bulk updates
        if (bid == 0) {
            double* y   = sh;            // [768]
            double* Wm  = sh + 768;      // [64][65]
            double* tmp = sh + 4928;     // [4][64]
            for (int i = tid; i < NEQ; i += NTHR) y[i] = g_rhs[i];
            __syncthreads();
            int r = tid & 63, qg = tid >> 6;
            for (int p = 0; p < 12; p++) {
                int o = p * 64;
                for (int i = tid; i < 4096; i += NTHR)
                    Wm[(i >> 6) * 65 + (i & 63)] = g_W[(size_t)p * 4096 + i];
                __syncthreads();
                double s = 0.0;
                for (int j = qg; j < 64; j += 4) s += Wm[j * 65 + r] * y[o + j];
                tmp[qg * 64 + r] = s;
                __syncthreads();
                if (tid < 64)
                    y[o + tid] = tmp[tid] + tmp[64 + tid] + tmp[128 + tid] + tmp[192 + tid];
                __syncthreads();
                for (int rr = o + 64 + warp; rr < NEQ; rr += 8) {
                    double s2 = 0.0;
#pragma unroll
                    for (int k = lane; k < 64; k += 32) s2 += g_ADA[(size_t)rr * NEQ + o + k] * y[o + k];
#pragma unroll
                    for (int off = 16; off; off >>= 1) s2 += __shfl_down_sync(0xffffffffu, s2, off);
                    if (lane == 0) y[rr] -= s2;
                }
                __syncthreads();
            }
            for (int p = 11; p >= 0; p--) {
                int o = p * 64;
                for (int i = tid; i < 4096; i += NTHR)
                    Wm[(i >> 6) * 65 + (i & 63)] = g_W[(size_t)p * 4096 + i];
                __syncthreads();
                double s = 0.0;
                for (int j = qg; j < 64; j += 4) s += Wm[r * 65 + j] * y[o + j];
                tmp[qg * 64 + r] = s;
                __syncthreads();
                if (tid < 64)
                    y[o + tid] = tmp[tid] + tmp[64 + tid] + tmp[128 + tid] + tmp[192 + tid];
                __syncthreads();
                for (int i = tid; i < o; i += NTHR) {
                    double s2 = 0.0;
#pragma unroll 8
                    for (int jj = 0; jj < 64; jj++) s2 += g_ADA[(size_t)(o + jj) * NEQ + i] * y[o + jj];
                    y[i] -= s2;
                }
                __syncthreads();
            }
            for (int i = tid; i < NEQ; i += NTHR) g_dnu[i] = y[i];
        }
        gsync(tgt);

        // 7) t = A^T dnu
        atmv_phase(sh, 1, bid, tid, warp, lane);
        gsync(tgt);

        // 8) stepA: dz, dlam, fraction-min partials, 4 dot partials (for next gap)
        if (bid < 16) {
            int i = bid * NTHR + tid;
            double rt = g_rtil[i], t2 = g_t[i], Di = g_Dinv[i];
            double rc = g_rc[i], la = g_lam[i], zz = g_z[i];
            double dz = (rt - t2) * Di;
            double dl = (-rc - la * dz) / zz;
            g_dz[i] = dz; g_dlam[i] = dl;
            double mn = INFINITY;
            if (dz < 0.0) mn = fmin(mn, -zz / dz);
            if (dl < 0.0) mn = fmin(mn, -la / dl);
            blk_min_to(mn, s_red, tid, &s_val);
            if (tid == 0) g_pmin[bid] = s_val;
            __syncthreads();
            blk_sum4_to(zz * la, zz * dl, dz * la, dz * dl, s_red, tid, bid);
        }
        gsync(tgt);
    }

    // ---- output: z_final = z + alpha_last * dz
    if (bid < 16) {
        double a = alpha_of();
        int i = bid * NTHR + tid;
        out[i] = (float)(g_z[i] + a * g_dz[i]);
    }
}

// ---------------- host launcher (2 graph nodes) ----------------
extern "C" void kernel_launch(void* const* d_in, const int* in_sizes, int n_in,
                              void* d_out, int out_size) {
    const float* puz  = (const float*)d_in[0];
    const void*  Araw = d_in[1];
    const float* logz = (const float*)d_in[2];
    float* out = (float*)d_out;

    static int attr_set = 0;
    if (!attr_set) {
        cudaFuncSetAttribute(k_main, cudaFuncAttributeMaxDynamicSharedMemorySize,
                             SMEM_DBL * (int)sizeof(double));
        attr_set = 1;
    }

    k_reset<<<1, 1>>>();
    k_main<<<NBLK, NTHR, SMEM_DBL * sizeof(double)>>>(puz, Araw, logz, out);
}